// round 15
// baseline (speedup 1.0000x reference)
#include <cuda_runtime.h>
#include <cuda_fp16.h>
#include <cstdint>

#define KT       2048
#define NH       96
#define M_TILE   64
#define KB       64
#define NITER    (KT / KB)     // 32
#define NTHREADS 256
#define NSTAGE   3

// W pre-packed into mma B-fragment layout (scratch __device__ global).
// Layout: [kc(32)][wn(4)][nt(3)][ldg(2)][lane(32)][8 halves]
//   halves within a thread's 16B: reg r = h>>1 (r: ks_l=r>>1, b=r&1), w=h&1
//   k   = kc*64 + (ldg*2 + (r>>1))*16 + (r&1)*8 + (lane&3)*2 + w
//   row = wn*24 + nt*8 + (lane>>2)
__device__ __half g_Wf[NH * KT];

// ---------------- SMEM layout per CTA (bytes) ----------------
#define SM_A     0u              // 3 x 8192   (64 rows x 128B, x fp16)
#define SM_TOTAL 24576u
#define A_STAGE  8192u

// ---------------- helpers ----------------
__device__ __forceinline__ uint32_t smem_u32(const void* p) {
    uint32_t a;
    asm("{ .reg .u64 t; cvta.to.shared.u64 t, %1; cvt.u32.u64 %0, t; }" : "=r"(a) : "l"(p));
    return a;
}
__device__ __forceinline__ uint32_t sw128(uint32_t o) { return o ^ ((o >> 3) & 0x70u); }

__device__ __forceinline__ void sts128(uint32_t a, uint32_t v0, uint32_t v1,
                                       uint32_t v2, uint32_t v3) {
    asm volatile("st.shared.v4.b32 [%0], {%1,%2,%3,%4};"
                 :: "r"(a), "r"(v0), "r"(v1), "r"(v2), "r"(v3) : "memory");
}
__device__ __forceinline__ void ldsm_x4(uint32_t* r, uint32_t addr) {
    asm volatile("ldmatrix.sync.aligned.m8n8.x4.shared.b16 {%0,%1,%2,%3}, [%4];"
                 : "=r"(r[0]), "=r"(r[1]), "=r"(r[2]), "=r"(r[3]) : "r"(addr));
}
__device__ __forceinline__ void mma16816(float* c, const uint32_t* a,
                                         uint32_t b0, uint32_t b1) {
    asm volatile(
        "mma.sync.aligned.m16n8k16.row.col.f32.f16.f16.f32 "
        "{%0,%1,%2,%3}, {%4,%5,%6,%7}, {%8,%9}, {%0,%1,%2,%3};"
        : "+f"(c[0]), "+f"(c[1]), "+f"(c[2]), "+f"(c[3])
        : "r"(a[0]), "r"(a[1]), "r"(a[2]), "r"(a[3]), "r"(b0), "r"(b1));
}

// ---------------- W fragment-pack pre-kernel ----------------
__global__ void __launch_bounds__(256) packW_kernel(const float* __restrict__ W) {
    int i = blockIdx.x * 256 + threadIdx.x;        // half index in g_Wf
    int h    = i & 7;
    int lane = (i >> 3) & 31;
    int blk  = i >> 8;           // (kc,wn,nt,ldg)
    int ldg  = blk & 1;
    int blk2 = blk >> 1;
    int nt   = blk2 % 3;
    int blk3 = blk2 / 3;
    int wn   = blk3 & 3;
    int kc   = blk3 >> 2;

    int r = h >> 1, w = h & 1;
    int ks = ldg * 2 + (r >> 1);
    int b  = r & 1;
    int k   = kc * KB + ks * 16 + b * 8 + (lane & 3) * 2 + w;
    int row = wn * 24 + nt * 8 + (lane >> 2);
    g_Wf[i] = __float2half(W[row * KT + k]);
}

// ---------------- main GEMM kernel ----------------
__global__ void __launch_bounds__(NTHREADS, 2)
mh96_kernel(const float* __restrict__ x, const float* __restrict__ bias,
            float* __restrict__ out)
{
    extern __shared__ __align__(1024) char smem[];
    const uint32_t sb = smem_u32(smem);
    const int tid = threadIdx.x;
    const int wid = tid >> 5;
    const int lid = tid & 31;
    const int m0  = blockIdx.x * M_TILE;

    const int wm = wid & 1;      // m-half: rows wm*32
    const int wn = wid >> 1;     // n-quarter: cols wn*24

    // raw f32 staging for x (distance-2 prefetch)
    float4 xr[2][2];

    auto loadXf = [&](int kc) {
#pragma unroll
        for (int j = 0; j < 2; ++j) {
            int s = j * NTHREADS + tid;          // 512 slots = 64 rows x 8 (16B units)
            int row = s >> 3, c8 = s & 7;
            const float4* p = reinterpret_cast<const float4*>(
                x + (size_t)(m0 + row) * KT + kc * KB + c8 * 8);
            xr[j][0] = p[0];
            xr[j][1] = p[1];
        }
    };
    auto cvtStsX = [&](int buf) {
#pragma unroll
        for (int j = 0; j < 2; ++j) {
            int s = j * NTHREADS + tid;
            int row = s >> 3, c8 = s & 7;
            uint32_t off = sw128((uint32_t)(row * 128 + c8 * 16));
            __half2 h0 = __float22half2_rn(make_float2(xr[j][0].x, xr[j][0].y));
            __half2 h1 = __float22half2_rn(make_float2(xr[j][0].z, xr[j][0].w));
            __half2 h2 = __float22half2_rn(make_float2(xr[j][1].x, xr[j][1].y));
            __half2 h3 = __float22half2_rn(make_float2(xr[j][1].z, xr[j][1].w));
            sts128(sb + SM_A + (uint32_t)buf * A_STAGE + off,
                   *reinterpret_cast<uint32_t*>(&h0), *reinterpret_cast<uint32_t*>(&h1),
                   *reinterpret_cast<uint32_t*>(&h2), *reinterpret_cast<uint32_t*>(&h3));
        }
    };

    float acc[2][3][4];
#pragma unroll
    for (int mt = 0; mt < 2; ++mt)
#pragma unroll
        for (int nt = 0; nt < 3; ++nt)
#pragma unroll
            for (int i = 0; i < 4; ++i) acc[mt][nt][i] = 0.f;

    // ldmatrix per-thread address components (A side)
    const int a_row8 = wm * 32 + (lid & 7) + ((lid >> 3) & 1) * 8;   // + mt*16
    const int a_koff = ((lid >> 4) & 1) * 16;                        // + ks*32

    // B fragment gmem base for this warp's n-slice + this lane
    const char* wf_lane = reinterpret_cast<const char*>(g_Wf) + (size_t)wn * 3072 + lid * 16;

    // ---------------- prologue ----------------
    loadXf(0);
    cvtStsX(0);                      // stalls on LDG(0) — prologue only
    loadXf(1);
    __syncthreads();                 // stage 0 ready

    for (int it = 0; it < NITER; ++it) {
        const int buf = it % NSTAGE;

        // B fragments for THIS iter: 6 coalesced LDG.128 from L2-resident g_Wf.
        // Issued first; consumed after cvtSts/loadX/ldsm (latency cover).
        const char* wf = wf_lane + (size_t)it * 12288;   // 4*3072 per kc
        uint4 u00 = *reinterpret_cast<const uint4*>(wf);
        uint4 u01 = *reinterpret_cast<const uint4*>(wf + 512);
        uint4 u10 = *reinterpret_cast<const uint4*>(wf + 1024);
        uint4 u11 = *reinterpret_cast<const uint4*>(wf + 1536);
        uint4 u20 = *reinterpret_cast<const uint4*>(wf + 2048);
        uint4 u21 = *reinterpret_cast<const uint4*>(wf + 2560);

        // stage it+1: convert + store x (LDG completed during previous iter)
        if (it + 1 < NITER) cvtStsX((it + 1) % NSTAGE);
        // stage it+2: issue x LDGs (a full iteration of slack)
        if (it + 2 < NITER) loadXf(it + 2);

        // spread B regs into compile-time-indexed array: bw[nt][2*ks+b]
        uint32_t bw[3][8];
        bw[0][0] = u00.x; bw[0][1] = u00.y; bw[0][2] = u00.z; bw[0][3] = u00.w;
        bw[0][4] = u01.x; bw[0][5] = u01.y; bw[0][6] = u01.z; bw[0][7] = u01.w;
        bw[1][0] = u10.x; bw[1][1] = u10.y; bw[1][2] = u10.z; bw[1][3] = u10.w;
        bw[1][4] = u11.x; bw[1][5] = u11.y; bw[1][6] = u11.z; bw[1][7] = u11.w;
        bw[2][0] = u20.x; bw[2][1] = u20.y; bw[2][2] = u20.z; bw[2][3] = u20.w;
        bw[2][4] = u21.x; bw[2][5] = u21.y; bw[2][6] = u21.z; bw[2][7] = u21.w;

        const uint32_t ah_b = sb + SM_A + (uint32_t)buf * A_STAGE;

#pragma unroll
        for (int ks = 0; ks < 4; ++ks) {
            uint32_t a[2][4];
#pragma unroll
            for (int mt = 0; mt < 2; ++mt) {
                uint32_t aoff = sw128((uint32_t)((a_row8 + mt * 16) * 128 + ks * 32 + a_koff));
                ldsm_x4(a[mt], ah_b + aoff);
            }
#pragma unroll
            for (int mt = 0; mt < 2; ++mt)
#pragma unroll
                for (int nt = 0; nt < 3; ++nt)
                    mma16816(acc[mt][nt], a[mt], bw[nt][2 * ks], bw[nt][2 * ks + 1]);
        }

        __syncthreads();
    }

    // ---------------- epilogue ----------------
    const int r0 = m0 + wm * 32 + (lid >> 2);
    const int c0 = wn * 24 + (lid & 3) * 2;
#pragma unroll
    for (int nt = 0; nt < 3; ++nt) {
        const int col = c0 + nt * 8;
        const float b0 = bias[col], b1 = bias[col + 1];
#pragma unroll
        for (int mt = 0; mt < 2; ++mt) {
            const int row = r0 + mt * 16;
            float2 v0 = make_float2(acc[mt][nt][0] + b0, acc[mt][nt][1] + b1);
            float2 v1 = make_float2(acc[mt][nt][2] + b0, acc[mt][nt][3] + b1);
            *reinterpret_cast<float2*>(out + (size_t)row * NH + col) = v0;
            *reinterpret_cast<float2*>(out + (size_t)(row + 8) * NH + col) = v1;
        }
    }
}

extern "C" void kernel_launch(void* const* d_in, const int* in_sizes, int n_in,
                              void* d_out, int out_size) {
    const float* x    = (const float*)d_in[0];  // [16384, 2048]
    const float* W    = (const float*)d_in[1];  // [96, 2048]
    const float* bias = (const float*)d_in[2];  // [96]
    float* out        = (float*)d_out;          // [16384, 96]

    cudaFuncSetAttribute(mh96_kernel, cudaFuncAttributeMaxDynamicSharedMemorySize, SM_TOTAL);
    packW_kernel<<<(NH * KT) / 256, 256>>>(W);
    mh96_kernel<<<16384 / M_TILE, NTHREADS, SM_TOTAL>>>(x, bias, out);
}

// round 16
// speedup vs baseline: 1.0856x; 1.0856x over previous
#include <cuda_runtime.h>
#include <cuda_fp16.h>
#include <cstdint>

#define KT       2048
#define NH       96
#define M_TILE   64
#define KB       64
#define NITER    (KT / KB)     // 32
#define NTHREADS 256
#define NSTAGE   3

// W pre-packed into mma B-fragment layout (scratch __device__ global).
// Layout: [kc(32)][wn(4)][nt(3)][ldg(2)][lane(32)][8 halves]
__device__ __half g_Wf[NH * KT];

// ---------------- SMEM layout per CTA (bytes) ----------------
#define SM_A     0u              // 3 x 8192   (64 rows x 128B, x fp16)
#define SM_TOTAL 24576u
#define A_STAGE  8192u

// ---------------- helpers ----------------
__device__ __forceinline__ uint32_t smem_u32(const void* p) {
    uint32_t a;
    asm("{ .reg .u64 t; cvta.to.shared.u64 t, %1; cvt.u32.u64 %0, t; }" : "=r"(a) : "l"(p));
    return a;
}
__device__ __forceinline__ uint32_t sw128(uint32_t o) { return o ^ ((o >> 3) & 0x70u); }

__device__ __forceinline__ void sts128(uint32_t a, uint32_t v0, uint32_t v1,
                                       uint32_t v2, uint32_t v3) {
    asm volatile("st.shared.v4.b32 [%0], {%1,%2,%3,%4};"
                 :: "r"(a), "r"(v0), "r"(v1), "r"(v2), "r"(v3) : "memory");
}
__device__ __forceinline__ void ldsm_x4(uint32_t* r, uint32_t addr) {
    asm volatile("ldmatrix.sync.aligned.m8n8.x4.shared.b16 {%0,%1,%2,%3}, [%4];"
                 : "=r"(r[0]), "=r"(r[1]), "=r"(r[2]), "=r"(r[3]) : "r"(addr));
}
__device__ __forceinline__ void mma16816(float* c, const uint32_t* a,
                                         uint32_t b0, uint32_t b1) {
    asm volatile(
        "mma.sync.aligned.m16n8k16.row.col.f32.f16.f16.f32 "
        "{%0,%1,%2,%3}, {%4,%5,%6,%7}, {%8,%9}, {%0,%1,%2,%3};"
        : "+f"(c[0]), "+f"(c[1]), "+f"(c[2]), "+f"(c[3])
        : "r"(a[0]), "r"(a[1]), "r"(a[2]), "r"(a[3]), "r"(b0), "r"(b1));
}

// ---------------- W fragment-pack pre-kernel ----------------
__global__ void __launch_bounds__(256) packW_kernel(const float* __restrict__ W) {
    int i = blockIdx.x * 256 + threadIdx.x;        // half index in g_Wf
    int h    = i & 7;
    int lane = (i >> 3) & 31;
    int blk  = i >> 8;           // (kc,wn,nt,ldg)
    int ldg  = blk & 1;
    int blk2 = blk >> 1;
    int nt   = blk2 % 3;
    int blk3 = blk2 / 3;
    int wn   = blk3 & 3;
    int kc   = blk3 >> 2;

    int r = h >> 1, w = h & 1;
    int ks = ldg * 2 + (r >> 1);
    int b  = r & 1;
    int k   = kc * KB + ks * 16 + b * 8 + (lane & 3) * 2 + w;
    int row = wn * 24 + nt * 8 + (lane >> 2);
    g_Wf[i] = __float2half(W[row * KT + k]);
}

// ---------------- main GEMM kernel ----------------
__global__ void __launch_bounds__(NTHREADS, 2)
mh96_kernel(const float* __restrict__ x, const float* __restrict__ bias,
            float* __restrict__ out)
{
    extern __shared__ __align__(1024) char smem[];
    const uint32_t sb = smem_u32(smem);
    const int tid = threadIdx.x;
    const int wid = tid >> 5;
    const int lid = tid & 31;
    const int m0  = blockIdx.x * M_TILE;

    const int wm = wid & 1;      // m-half: rows wm*32
    const int wn = wid >> 1;     // n-quarter: cols wn*24

    // raw f32 staging for x (distance-2 prefetch)
    float4 xr[2][2];

    auto loadXf = [&](int kc) {
#pragma unroll
        for (int j = 0; j < 2; ++j) {
            int s = j * NTHREADS + tid;          // 512 slots = 64 rows x 8 (16B units)
            int row = s >> 3, c8 = s & 7;
            const float4* p = reinterpret_cast<const float4*>(
                x + (size_t)(m0 + row) * KT + kc * KB + c8 * 8);
            xr[j][0] = p[0];
            xr[j][1] = p[1];
        }
    };
    auto cvtStsX = [&](int buf) {
#pragma unroll
        for (int j = 0; j < 2; ++j) {
            int s = j * NTHREADS + tid;
            int row = s >> 3, c8 = s & 7;
            uint32_t off = sw128((uint32_t)(row * 128 + c8 * 16));
            __half2 h0 = __float22half2_rn(make_float2(xr[j][0].x, xr[j][0].y));
            __half2 h1 = __float22half2_rn(make_float2(xr[j][0].z, xr[j][0].w));
            __half2 h2 = __float22half2_rn(make_float2(xr[j][1].x, xr[j][1].y));
            __half2 h3 = __float22half2_rn(make_float2(xr[j][1].z, xr[j][1].w));
            sts128(sb + SM_A + (uint32_t)buf * A_STAGE + off,
                   *reinterpret_cast<uint32_t*>(&h0), *reinterpret_cast<uint32_t*>(&h1),
                   *reinterpret_cast<uint32_t*>(&h2), *reinterpret_cast<uint32_t*>(&h3));
        }
    };

    // B fragment gmem base for this warp's n-slice + this lane
    const char* wf_lane = reinterpret_cast<const char*>(g_Wf) + (size_t)wn * 3072 + lid * 16;

    // B fragment register sets (bw[nt][2*ks+b]); LDG a full iteration ahead
    uint32_t bw0[3][8], bw1[3][8];
    auto loadB = [&](int kc, uint32_t (*bw)[8]) {
        const char* wf = wf_lane + (size_t)kc * 12288;
        uint4 u00 = *reinterpret_cast<const uint4*>(wf);
        uint4 u01 = *reinterpret_cast<const uint4*>(wf + 512);
        uint4 u10 = *reinterpret_cast<const uint4*>(wf + 1024);
        uint4 u11 = *reinterpret_cast<const uint4*>(wf + 1536);
        uint4 u20 = *reinterpret_cast<const uint4*>(wf + 2048);
        uint4 u21 = *reinterpret_cast<const uint4*>(wf + 2560);
        bw[0][0] = u00.x; bw[0][1] = u00.y; bw[0][2] = u00.z; bw[0][3] = u00.w;
        bw[0][4] = u01.x; bw[0][5] = u01.y; bw[0][6] = u01.z; bw[0][7] = u01.w;
        bw[1][0] = u10.x; bw[1][1] = u10.y; bw[1][2] = u10.z; bw[1][3] = u10.w;
        bw[1][4] = u11.x; bw[1][5] = u11.y; bw[1][6] = u11.z; bw[1][7] = u11.w;
        bw[2][0] = u20.x; bw[2][1] = u20.y; bw[2][2] = u20.z; bw[2][3] = u20.w;
        bw[2][4] = u21.x; bw[2][5] = u21.y; bw[2][6] = u21.z; bw[2][7] = u21.w;
    };

    float acc[2][3][4];
#pragma unroll
    for (int mt = 0; mt < 2; ++mt)
#pragma unroll
        for (int nt = 0; nt < 3; ++nt)
#pragma unroll
            for (int i = 0; i < 4; ++i) acc[mt][nt][i] = 0.f;

    // ldmatrix per-thread address components (A side)
    const int a_row8 = wm * 32 + (lid & 7) + ((lid >> 3) & 1) * 8;   // + mt*16
    const int a_koff = ((lid >> 4) & 1) * 16;                        // + ks*32

    // mma body for one iteration (compile-time bw indices)
    auto mmaIter = [&](int it, uint32_t (*bw)[8]) {
        const uint32_t ah_b = sb + SM_A + (uint32_t)(it % NSTAGE) * A_STAGE;
#pragma unroll
        for (int ks = 0; ks < 4; ++ks) {
            uint32_t a[2][4];
#pragma unroll
            for (int mt = 0; mt < 2; ++mt) {
                uint32_t aoff = sw128((uint32_t)((a_row8 + mt * 16) * 128 + ks * 32 + a_koff));
                ldsm_x4(a[mt], ah_b + aoff);
            }
#pragma unroll
            for (int mt = 0; mt < 2; ++mt)
#pragma unroll
                for (int nt = 0; nt < 3; ++nt)
                    mma16816(acc[mt][nt], a[mt], bw[nt][2 * ks], bw[nt][2 * ks + 1]);
        }
    };

    // ---------------- prologue ----------------
    loadXf(0);
    loadB(0, bw0);                   // B(0): has the whole prologue to land
    cvtStsX(0);                      // stalls on LDG x(0) — prologue only
    loadXf(1);
    __syncthreads();                 // stage 0 ready

    // main loop unrolled by 2: alternate bw0/bw1 (NITER = 32, even)
    for (int it2 = 0; it2 < NITER; it2 += 2) {
        // -------- even iteration: consume bw0, prefetch bw1 <- B(it2+1) --------
        loadB(it2 + 1, bw1);                       // full iteration of slack
        cvtStsX((it2 + 1) % NSTAGE);               // x stage it2+1 (it2+1 < NITER always)
        if (it2 + 2 < NITER) loadXf(it2 + 2);
        mmaIter(it2, bw0);
        __syncthreads();

        // -------- odd iteration: consume bw1, prefetch bw0 <- B(it2+2) --------
        if (it2 + 2 < NITER) {
            loadB(it2 + 2, bw0);
            cvtStsX((it2 + 2) % NSTAGE);
            if (it2 + 3 < NITER) loadXf(it2 + 3);
        }
        mmaIter(it2 + 1, bw1);
        __syncthreads();
    }

    // ---------------- epilogue ----------------
    const int r0 = m0 + wm * 32 + (lid >> 2);
    const int c0 = wn * 24 + (lid & 3) * 2;
#pragma unroll
    for (int nt = 0; nt < 3; ++nt) {
        const int col = c0 + nt * 8;
        const float b0 = bias[col], b1 = bias[col + 1];
#pragma unroll
        for (int mt = 0; mt < 2; ++mt) {
            const int row = r0 + mt * 16;
            float2 v0 = make_float2(acc[mt][nt][0] + b0, acc[mt][nt][1] + b1);
            float2 v1 = make_float2(acc[mt][nt][2] + b0, acc[mt][nt][3] + b1);
            *reinterpret_cast<float2*>(out + (size_t)row * NH + col) = v0;
            *reinterpret_cast<float2*>(out + (size_t)(row + 8) * NH + col) = v1;
        }
    }
}

extern "C" void kernel_launch(void* const* d_in, const int* in_sizes, int n_in,
                              void* d_out, int out_size) {
    const float* x    = (const float*)d_in[0];  // [16384, 2048]
    const float* W    = (const float*)d_in[1];  // [96, 2048]
    const float* bias = (const float*)d_in[2];  // [96]
    float* out        = (float*)d_out;          // [16384, 96]

    cudaFuncSetAttribute(mh96_kernel, cudaFuncAttributeMaxDynamicSharedMemorySize, SM_TOTAL);
    packW_kernel<<<(NH * KT) / 256, 256>>>(W);
    mh96_kernel<<<16384 / M_TILE, NTHREADS, SM_TOTAL>>>(x, bias, out);
}

// round 17
// speedup vs baseline: 1.1797x; 1.0866x over previous
#include <cuda_runtime.h>
#include <cuda_fp16.h>
#include <cstdint>

#define KT       2048
#define NH       96
#define M_TILE   64
#define KB       64
#define NITER    (KT / KB)     // 32
#define NTHREADS 256
#define NSTAGE   4

// Preconverted W (fp16) — scratch via __device__ global, no allocation
__device__ __half g_Whi[NH * KT];

// ---------------- SMEM layout per CTA (bytes) ----------------
#define SM_A     0u              // 4 x 8192   (64 rows x 128B, x fp16)
#define SM_B     32768u          // 4 x 12288  (96 rows x 128B, W fp16)
#define SM_TOTAL 81920u
#define A_STAGE  8192u
#define B_STAGE  12288u

// ---------------- helpers ----------------
__device__ __forceinline__ uint32_t smem_u32(const void* p) {
    uint32_t a;
    asm("{ .reg .u64 t; cvta.to.shared.u64 t, %1; cvt.u32.u64 %0, t; }" : "=r"(a) : "l"(p));
    return a;
}
__device__ __forceinline__ uint32_t sw128(uint32_t o) { return o ^ ((o >> 3) & 0x70u); }

__device__ __forceinline__ void sts128(uint32_t a, uint32_t v0, uint32_t v1,
                                       uint32_t v2, uint32_t v3) {
    asm volatile("st.shared.v4.b32 [%0], {%1,%2,%3,%4};"
                 :: "r"(a), "r"(v0), "r"(v1), "r"(v2), "r"(v3) : "memory");
}
__device__ __forceinline__ void cp16(uint32_t dst, const void* src) {
    asm volatile("cp.async.cg.shared.global [%0], [%1], 16;"
                 :: "r"(dst), "l"(src) : "memory");
}
__device__ __forceinline__ void cp_commit() {
    asm volatile("cp.async.commit_group;" ::: "memory");
}
__device__ __forceinline__ void cp_wait0() {
    asm volatile("cp.async.wait_group 0;" ::: "memory");
}
__device__ __forceinline__ void ldsm_x4(uint32_t* r, uint32_t addr) {
    asm volatile("ldmatrix.sync.aligned.m8n8.x4.shared.b16 {%0,%1,%2,%3}, [%4];"
                 : "=r"(r[0]), "=r"(r[1]), "=r"(r[2]), "=r"(r[3]) : "r"(addr));
}
__device__ __forceinline__ void mma16816(float* c, const uint32_t* a,
                                         uint32_t b0, uint32_t b1) {
    asm volatile(
        "mma.sync.aligned.m16n8k16.row.col.f32.f16.f16.f32 "
        "{%0,%1,%2,%3}, {%4,%5,%6,%7}, {%8,%9}, {%0,%1,%2,%3};"
        : "+f"(c[0]), "+f"(c[1]), "+f"(c[2]), "+f"(c[3])
        : "r"(a[0]), "r"(a[1]), "r"(a[2]), "r"(a[3]), "r"(b0), "r"(b1));
}

// ---------------- W pre-convert kernel ----------------
__global__ void __launch_bounds__(256) convW_kernel(const float* __restrict__ W) {
    int i = blockIdx.x * 256 + threadIdx.x;
    g_Whi[i] = __float2half(W[i]);
}

// ---------------- main GEMM kernel ----------------
__global__ void __launch_bounds__(NTHREADS, 2)
mh96_kernel(const float* __restrict__ x, const float* __restrict__ bias,
            float* __restrict__ out)
{
    extern __shared__ __align__(1024) char smem[];
    const uint32_t sb = smem_u32(smem);
    const int tid = threadIdx.x;
    const int wid = tid >> 5;
    const int lid = tid & 31;
    const int m0  = blockIdx.x * M_TILE;

    const int wm = wid & 1;      // m-half: rows wm*32
    const int wn = wid >> 1;     // n-quarter: cols wn*24

    // raw f32 staging for x (consumed by cvtSts one iter after load)
    float4 xr[2][2];

    auto loadXf = [&](int kc) {      // issue LDGs only
#pragma unroll
        for (int j = 0; j < 2; ++j) {
            int s = j * NTHREADS + tid;          // 512 slots = 64 rows x 8 (16B units)
            int row = s >> 3, c8 = s & 7;
            const float4* p = reinterpret_cast<const float4*>(
                x + (size_t)(m0 + row) * KT + kc * KB + c8 * 8);
            xr[j][0] = p[0];
            xr[j][1] = p[1];
        }
    };
    auto cpW = [&](int kc, int buf) {
#pragma unroll
        for (int j = 0; j < 3; ++j) {
            int s = j * NTHREADS + tid;          // 768 slots = 96 rows x 8
            int row = s >> 3, c8 = s & 7;
            uint32_t off = sw128((uint32_t)(row * 128 + c8 * 16));
            size_t go = (size_t)row * KT + kc * KB + c8 * 8;
            cp16(sb + SM_B + (uint32_t)buf * B_STAGE + off, g_Whi + go);
        }
    };
    auto cvtStsX = [&](int buf) {    // convert staged f32 -> half2, store to ring buf
#pragma unroll
        for (int j = 0; j < 2; ++j) {
            int s = j * NTHREADS + tid;
            int row = s >> 3, c8 = s & 7;
            uint32_t off = sw128((uint32_t)(row * 128 + c8 * 16));
            __half2 h0 = __float22half2_rn(make_float2(xr[j][0].x, xr[j][0].y));
            __half2 h1 = __float22half2_rn(make_float2(xr[j][0].z, xr[j][0].w));
            __half2 h2 = __float22half2_rn(make_float2(xr[j][1].x, xr[j][1].y));
            __half2 h3 = __float22half2_rn(make_float2(xr[j][1].z, xr[j][1].w));
            sts128(sb + SM_A + (uint32_t)buf * A_STAGE + off,
                   *reinterpret_cast<uint32_t*>(&h0), *reinterpret_cast<uint32_t*>(&h1),
                   *reinterpret_cast<uint32_t*>(&h2), *reinterpret_cast<uint32_t*>(&h3));
        }
    };

    float acc[2][3][4];
#pragma unroll
    for (int mt = 0; mt < 2; ++mt)
#pragma unroll
        for (int nt = 0; nt < 3; ++nt)
#pragma unroll
            for (int i = 0; i < 4; ++i) acc[mt][nt][i] = 0.f;

    // ldmatrix per-thread address components
    const int a_row8 = wm * 32 + (lid & 7) + ((lid >> 3) & 1) * 8;   // + mt*16
    const int a_koff = ((lid >> 4) & 1) * 16;                        // + ks*32
    const int b_row  = wn * 24 + (lid & 7);                          // + nt*8
    const int b_koff = (lid >> 3) * 16;                              // + kp*64

    auto mmaIter = [&](int it) {
        const uint32_t ah_b = sb + SM_A + (uint32_t)(it % NSTAGE) * A_STAGE;
        const uint32_t bh_b = sb + SM_B + (uint32_t)(it % NSTAGE) * B_STAGE;
#pragma unroll
        for (int kp = 0; kp < 2; ++kp) {
            uint32_t bh[3][4];
#pragma unroll
            for (int nt = 0; nt < 3; ++nt) {
                uint32_t boff = sw128((uint32_t)((b_row + nt * 8) * 128 + kp * 64 + b_koff));
                ldsm_x4(bh[nt], bh_b + boff);
            }
#pragma unroll
            for (int ks2 = 0; ks2 < 2; ++ks2) {
                const int ks = kp * 2 + ks2;
                uint32_t a[2][4];
#pragma unroll
                for (int mt = 0; mt < 2; ++mt) {
                    uint32_t aoff = sw128((uint32_t)((a_row8 + mt * 16) * 128 + ks * 32 + a_koff));
                    ldsm_x4(a[mt], ah_b + aoff);
                }
#pragma unroll
                for (int mt = 0; mt < 2; ++mt)
#pragma unroll
                    for (int nt = 0; nt < 3; ++nt)
                        mma16816(acc[mt][nt], a[mt], bh[nt][2 * ks2], bh[nt][2 * ks2 + 1]);
            }
        }
    };

    // ---------------- prologue: fill stages 0,1; xr <- chunk 2 ----------------
    loadXf(0);
    cpW(0, 0);  cp_commit();
    cvtStsX(0);                      // stalls on LDG(0) — prologue only
    loadXf(1);
    cpW(1, 1);  cp_commit();
    cvtStsX(1);                      // stalls on LDG(1) — prologue only
    loadXf(2);                       // xr <- chunk 2 (in flight)
    cp_wait0();                      // W(0), W(1) complete
    __syncthreads();                 // stages 0,1 ready

    // main loop: barrier every 2 iterations (4-stage ring, distance-2 writes)
    for (int e = 0; e < NITER; e += 2) {
        // ---- even iteration e ----
        if (e + 2 < NITER) { cpW(e + 2, (e + 2) % NSTAGE); cp_commit(); }
        if (e + 2 < NITER) cvtStsX((e + 2) % NSTAGE);   // uses xr(e+2), loaded prev iter
        if (e + 3 < NITER) loadXf(e + 3);               // xr <- e+3
        mmaIter(e);                                     // reads stage e%4 (no barrier after)

        // ---- odd iteration e+1 ----
        if (e + 3 < NITER) { cpW(e + 3, (e + 3) % NSTAGE); cp_commit(); }
        if (e + 3 < NITER) cvtStsX((e + 3) % NSTAGE);   // uses xr(e+3)
        if (e + 4 < NITER) loadXf(e + 4);               // xr <- e+4
        mmaIter(e + 1);                                 // reads stage (e+1)%4

        cp_wait0();                  // all outstanding W groups arrived
        __syncthreads();             // stages e+2, e+3 published; ring slots e, e+1 reusable
    }

    // ---------------- epilogue ----------------
    const int r0 = m0 + wm * 32 + (lid >> 2);
    const int c0 = wn * 24 + (lid & 3) * 2;
#pragma unroll
    for (int nt = 0; nt < 3; ++nt) {
        const int col = c0 + nt * 8;
        const float b0 = bias[col], b1 = bias[col + 1];
#pragma unroll
        for (int mt = 0; mt < 2; ++mt) {
            const int row = r0 + mt * 16;
            float2 v0 = make_float2(acc[mt][nt][0] + b0, acc[mt][nt][1] + b1);
            float2 v1 = make_float2(acc[mt][nt][2] + b0, acc[mt][nt][3] + b1);
            *reinterpret_cast<float2*>(out + (size_t)row * NH + col) = v0;
            *reinterpret_cast<float2*>(out + (size_t)(row + 8) * NH + col) = v1;
        }
    }
}

extern "C" void kernel_launch(void* const* d_in, const int* in_sizes, int n_in,
                              void* d_out, int out_size) {
    const float* x    = (const float*)d_in[0];  // [16384, 2048]
    const float* W    = (const float*)d_in[1];  // [96, 2048]
    const float* bias = (const float*)d_in[2];  // [96]
    float* out        = (float*)d_out;          // [16384, 96]

    cudaFuncSetAttribute(mh96_kernel, cudaFuncAttributeMaxDynamicSharedMemorySize, SM_TOTAL);
    convW_kernel<<<(NH * KT) / 256, 256>>>(W);
    mh96_kernel<<<16384 / M_TILE, NTHREADS, SM_TOTAL>>>(x, bias, out);
}